// round 2
// baseline (speedup 1.0000x reference)
#include <cuda_runtime.h>

// Problem constants
#define BB 64      // batch
#define SS 256     // seq length
#define VV 2048    // ntokens
#define HH 512     // nhid

// Scratch (no allocations allowed)
__device__ float g_h1[BB * HH];     // relu(gather-sum + b1)
__device__ float g_h2pre[BB * HH];  // h1 @ W2 accumulator (pre bias/relu)

// ---------------------------------------------------------------------------
// K1: gather-sum -> h1, plus zero h2pre and init out = b3.
// grid = 256 (64 batches x 4 H-chunks), block = 128 threads (one h each).
// Handles both int64 and int32 index layouts (runtime-detected).
// ---------------------------------------------------------------------------
__global__ void k_gather(const int* __restrict__ x32,
                         const float* __restrict__ W1,
                         const float* __restrict__ b1,
                         const float* __restrict__ b3,
                         float* __restrict__ out) {
    const int t = threadIdx.x;
    const int gid = blockIdx.x * 128 + t;   // 0..32767

    // Side work: zero the GEMM1 accumulator; seed out with b3.
    g_h2pre[gid] = 0.0f;
    if (gid < BB * SS) out[gid] = b3[gid & (SS - 1)];

    // Detect index dtype: int64 -> every odd 32-bit word of the first 128
    // elements is 0 (values < 2048). Safe region for both layouts.
    __shared__ int s_is64;
    if (t == 0) s_is64 = 1;
    __syncthreads();
    if (x32[2 * t + 1] != 0) s_is64 = 0;   // racy store of same value: fine
    __syncthreads();
    const int is64 = s_is64;

    const int b = blockIdx.x >> 2;                    // batch
    const int h = ((blockIdx.x & 3) << 7) | t;        // 0..511

    // Row base offsets (in floats) for this batch's 256 gathered rows.
    __shared__ unsigned rb[SS];
    if (is64) {
        const long long* x64 = (const long long*)x32;
        for (int i = t; i < SS; i += 128) {
            unsigned tok = (unsigned)x64[b * SS + i];
            rb[i] = (tok + (unsigned)i * VV) << 9;    // *HH
        }
    } else {
        for (int i = t; i < SS; i += 128) {
            unsigned tok = (unsigned)x32[b * SS + i];
            rb[i] = (tok + (unsigned)i * VV) << 9;
        }
    }
    __syncthreads();

    float a0 = 0.f, a1 = 0.f, a2 = 0.f, a3 = 0.f;
    #pragma unroll 4
    for (int p = 0; p < SS; p += 4) {
        a0 += W1[rb[p + 0] + h];
        a1 += W1[rb[p + 1] + h];
        a2 += W1[rb[p + 2] + h];
        a3 += W1[rb[p + 3] + h];
    }
    float s = (a0 + a1) + (a2 + a3) + b1[h];
    g_h1[b * HH + h] = fmaxf(s, 0.0f);
}

// ---------------------------------------------------------------------------
// K2: GEMM1 partial: h2pre += h1(64x512) @ W2(512x512), K-split.
// grid = (16 n-tiles of 32, 8 k-splits of 64), block = 128 threads.
// Each thread: 4x4 register tile. atomicAdd epilogue into g_h2pre.
// ---------------------------------------------------------------------------
__global__ void k_gemm1(const float* __restrict__ W2) {
    const int nb = blockIdx.x * 32;
    const int kb = blockIdx.y * 64;
    const int t = threadIdx.x;
    const int m4 = (t >> 3) * 4;    // 0..60
    const int n4 = (t & 7) * 4;     // 0..28

    __shared__ float As[64][33];                     // padded: conflict-free
    __shared__ __align__(16) float Bs[32][32];

    float acc[4][4] = {};

    for (int kk = 0; kk < 64; kk += 32) {
        // Stage A: h1[0..63][kb+kk .. +32), coalesced.
        #pragma unroll
        for (int i = 0; i < 16; i++) {
            int idx = i * 128 + t;
            int m = idx >> 5, k = idx & 31;
            As[m][k] = g_h1[m * HH + kb + kk + k];
        }
        // Stage B: W2[kb+kk..+32)[nb..nb+32), coalesced.
        #pragma unroll
        for (int i = 0; i < 8; i++) {
            int idx = i * 128 + t;
            int k = idx >> 5, n = idx & 31;
            Bs[k][n] = W2[(kb + kk + k) * HH + nb + n];
        }
        __syncthreads();

        #pragma unroll
        for (int k = 0; k < 32; k++) {
            float4 b4 = *(const float4*)&Bs[k][n4];
            float a0 = As[m4 + 0][k];
            float a1 = As[m4 + 1][k];
            float a2 = As[m4 + 2][k];
            float a3 = As[m4 + 3][k];
            acc[0][0] += a0 * b4.x; acc[0][1] += a0 * b4.y; acc[0][2] += a0 * b4.z; acc[0][3] += a0 * b4.w;
            acc[1][0] += a1 * b4.x; acc[1][1] += a1 * b4.y; acc[1][2] += a1 * b4.z; acc[1][3] += a1 * b4.w;
            acc[2][0] += a2 * b4.x; acc[2][1] += a2 * b4.y; acc[2][2] += a2 * b4.z; acc[2][3] += a2 * b4.w;
            acc[3][0] += a3 * b4.x; acc[3][1] += a3 * b4.y; acc[3][2] += a3 * b4.z; acc[3][3] += a3 * b4.w;
        }
        __syncthreads();
    }

    #pragma unroll
    for (int i = 0; i < 4; i++)
        #pragma unroll
        for (int j = 0; j < 4; j++)
            atomicAdd(&g_h2pre[(m4 + i) * HH + nb + n4 + j], acc[i][j]);
}

// ---------------------------------------------------------------------------
// K3: GEMM2 with fused relu(h2pre + b2) on the A side:
//   out += relu(h2pre + b2)(64x512) @ W3(512x256), K-split.
// grid = (8 n-tiles of 32, 8 k-splits of 64), block = 128 threads.
// out was pre-initialized to b3 by K1.
// ---------------------------------------------------------------------------
__global__ void k_gemm2(const float* __restrict__ b2,
                        const float* __restrict__ W3,
                        float* __restrict__ out) {
    const int nb = blockIdx.x * 32;
    const int kb = blockIdx.y * 64;
    const int t = threadIdx.x;
    const int m4 = (t >> 3) * 4;
    const int n4 = (t & 7) * 4;

    __shared__ float As[64][33];
    __shared__ __align__(16) float Bs[32][32];

    float acc[4][4] = {};

    for (int kk = 0; kk < 64; kk += 32) {
        #pragma unroll
        for (int i = 0; i < 16; i++) {
            int idx = i * 128 + t;
            int m = idx >> 5, k = idx & 31;
            int kg = kb + kk + k;
            As[m][k] = fmaxf(g_h2pre[m * HH + kg] + b2[kg], 0.0f);
        }
        #pragma unroll
        for (int i = 0; i < 8; i++) {
            int idx = i * 128 + t;
            int k = idx >> 5, n = idx & 31;
            Bs[k][n] = W3[(kb + kk + k) * SS + nb + n];
        }
        __syncthreads();

        #pragma unroll
        for (int k = 0; k < 32; k++) {
            float4 b4 = *(const float4*)&Bs[k][n4];
            float a0 = As[m4 + 0][k];
            float a1 = As[m4 + 1][k];
            float a2 = As[m4 + 2][k];
            float a3 = As[m4 + 3][k];
            acc[0][0] += a0 * b4.x; acc[0][1] += a0 * b4.y; acc[0][2] += a0 * b4.z; acc[0][3] += a0 * b4.w;
            acc[1][0] += a1 * b4.x; acc[1][1] += a1 * b4.y; acc[1][2] += a1 * b4.z; acc[1][3] += a1 * b4.w;
            acc[2][0] += a2 * b4.x; acc[2][1] += a2 * b4.y; acc[2][2] += a2 * b4.z; acc[2][3] += a2 * b4.w;
            acc[3][0] += a3 * b4.x; acc[3][1] += a3 * b4.y; acc[3][2] += a3 * b4.z; acc[3][3] += a3 * b4.w;
        }
        __syncthreads();
    }

    #pragma unroll
    for (int i = 0; i < 4; i++)
        #pragma unroll
        for (int j = 0; j < 4; j++)
            atomicAdd(&out[(m4 + i) * SS + nb + n4 + j], acc[i][j]);
}

// ---------------------------------------------------------------------------
extern "C" void kernel_launch(void* const* d_in, const int* in_sizes, int n_in,
                              void* d_out, int out_size) {
    const int*   x  = (const int*)d_in[0];     // int32 or int64, detected on device
    const float* W1 = (const float*)d_in[1];
    const float* b1 = (const float*)d_in[2];
    const float* W2 = (const float*)d_in[3];
    const float* b2 = (const float*)d_in[4];
    const float* W3 = (const float*)d_in[5];
    const float* b3 = (const float*)d_in[6];
    float* out = (float*)d_out;

    k_gather<<<256, 128>>>(x, W1, b1, b3, out);
    k_gemm1<<<dim3(16, 8), 128>>>(W2);
    k_gemm2<<<dim3(8, 8), 128>>>(b2, W3, out);
}

// round 4
// speedup vs baseline: 1.1212x; 1.1212x over previous
#include <cuda_runtime.h>

// Problem constants
#define BB 64      // batch
#define SS 256     // seq length
#define VV 2048    // ntokens
#define HH 512     // nhid
#define NSPLIT 8   // sequence splits for the gather
#define SP (SS / NSPLIT)   // positions per gather CTA = 32

// Scratch (no allocations allowed). __device__ globals are zero-initialized
// at module load; g_h1pre is re-zeroed by K3 at the end of every call, so the
// "starts at zero" invariant holds across graph replays.
__device__ float g_h1pre[BB * HH];  // gather-sum accumulator (pre bias/relu)
__device__ float g_h2pre[BB * HH];  // h1 @ W2 accumulator   (pre bias/relu)

// ---------------------------------------------------------------------------
// K1: gather partial-sum -> atomicAdd into g_h1pre.
// grid = (256, 8): x = 64 batches x 4 H-chunks, y = 8 seq-splits of 32.
// block = 128 threads (one h column each). Also (on y==0 slice) zeroes
// g_h2pre and seeds out = b3.
// Handles both int64 and int32 index layouts (runtime-detected).
// ---------------------------------------------------------------------------
__global__ void k_gather(const int* __restrict__ x32,
                         const float* __restrict__ W1,
                         const float* __restrict__ b3,
                         float* __restrict__ out) {
    const int t = threadIdx.x;

    // Side work (only the y==0 slice): zero GEMM1 accumulator, seed out.
    if (blockIdx.y == 0) {
        const int gid = blockIdx.x * 128 + t;        // 0..32767
        g_h2pre[gid] = 0.0f;
        if (gid < BB * SS) out[gid] = b3[gid & (SS - 1)];
    }

    // Detect index dtype: int64 -> every odd 32-bit word of the first 128
    // elements is 0 (token values < 2048). Safe under both layouts.
    __shared__ int s_is64;
    if (t == 0) s_is64 = 1;
    __syncthreads();
    if (x32[2 * t + 1] != 0) s_is64 = 0;   // racy same-value store: fine
    __syncthreads();
    const int is64 = s_is64;

    const int b  = blockIdx.x >> 2;                   // batch
    const int h  = ((blockIdx.x & 3) << 7) | t;       // 0..511
    const int p0 = blockIdx.y * SP;                   // first position

    // Row base offsets (in floats) for this CTA's 32 gathered rows.
    __shared__ unsigned rb[SP];
    if (t < SP) {
        unsigned tok;
        if (is64) tok = (unsigned)((const long long*)x32)[b * SS + p0 + t];
        else      tok = (unsigned)x32[b * SS + p0 + t];
        rb[t] = (tok + (unsigned)(p0 + t) * VV) << 9;   // * HH
    }
    __syncthreads();

    float a0 = 0.f, a1 = 0.f, a2 = 0.f, a3 = 0.f;
    #pragma unroll
    for (int p = 0; p < SP; p += 4) {
        a0 += W1[rb[p + 0] + h];
        a1 += W1[rb[p + 1] + h];
        a2 += W1[rb[p + 2] + h];
        a3 += W1[rb[p + 3] + h];
    }
    atomicAdd(&g_h1pre[b * HH + h], (a0 + a1) + (a2 + a3));
}

// ---------------------------------------------------------------------------
// K2: GEMM1 partial: h2pre += relu(h1pre + b1)(64x512) @ W2(512x512), K-split.
// grid = (16 n-tiles of 32, 8 k-splits of 64), block = 128 threads.
// Bias + ReLU for h1 fused into the A-staging.
// ---------------------------------------------------------------------------
__global__ void k_gemm1(const float* __restrict__ b1,
                        const float* __restrict__ W2) {
    const int nb = blockIdx.x * 32;
    const int kb = blockIdx.y * 64;
    const int t = threadIdx.x;
    const int m4 = (t >> 3) * 4;    // 0..60
    const int n4 = (t & 7) * 4;     // 0..28

    __shared__ float As[64][33];                     // padded: conflict-free
    __shared__ __align__(16) float Bs[32][32];

    float acc[4][4] = {};

    for (int kk = 0; kk < 64; kk += 32) {
        #pragma unroll
        for (int i = 0; i < 16; i++) {
            int idx = i * 128 + t;
            int m = idx >> 5, k = idx & 31;
            int kg = kb + kk + k;
            As[m][k] = fmaxf(g_h1pre[m * HH + kg] + b1[kg], 0.0f);
        }
        #pragma unroll
        for (int i = 0; i < 8; i++) {
            int idx = i * 128 + t;
            int k = idx >> 5, n = idx & 31;
            Bs[k][n] = W2[(kb + kk + k) * HH + nb + n];
        }
        __syncthreads();

        #pragma unroll
        for (int k = 0; k < 32; k++) {
            float4 b4 = *(const float4*)&Bs[k][n4];
            float a0 = As[m4 + 0][k];
            float a1 = As[m4 + 1][k];
            float a2 = As[m4 + 2][k];
            float a3 = As[m4 + 3][k];
            acc[0][0] += a0 * b4.x; acc[0][1] += a0 * b4.y; acc[0][2] += a0 * b4.z; acc[0][3] += a0 * b4.w;
            acc[1][0] += a1 * b4.x; acc[1][1] += a1 * b4.y; acc[1][2] += a1 * b4.z; acc[1][3] += a1 * b4.w;
            acc[2][0] += a2 * b4.x; acc[2][1] += a2 * b4.y; acc[2][2] += a2 * b4.z; acc[2][3] += a2 * b4.w;
            acc[3][0] += a3 * b4.x; acc[3][1] += a3 * b4.y; acc[3][2] += a3 * b4.z; acc[3][3] += a3 * b4.w;
        }
        __syncthreads();
    }

    #pragma unroll
    for (int i = 0; i < 4; i++)
        #pragma unroll
        for (int j = 0; j < 4; j++)
            atomicAdd(&g_h2pre[(m4 + i) * HH + nb + n4 + j], acc[i][j]);
}

// ---------------------------------------------------------------------------
// K3: GEMM2 with fused relu(h2pre + b2) on the A side:
//   out += relu(h2pre + b2)(64x512) @ W3(512x256), K-split.
// grid = (8 n-tiles of 32, 8 k-splits of 64), block = 128 threads.
// out was pre-initialized to b3 by K1.  Also re-zeroes g_h1pre for the next
// graph replay (stream-ordered after K2, which is its last reader).
// ---------------------------------------------------------------------------
__global__ void k_gemm2(const float* __restrict__ b2,
                        const float* __restrict__ W3,
                        float* __restrict__ out) {
    const int nb = blockIdx.x * 32;
    const int kb = blockIdx.y * 64;
    const int t = threadIdx.x;
    const int m4 = (t >> 3) * 4;
    const int n4 = (t & 7) * 4;

    __shared__ float As[64][33];
    __shared__ __align__(16) float Bs[32][32];

    float acc[4][4] = {};

    for (int kk = 0; kk < 64; kk += 32) {
        #pragma unroll
        for (int i = 0; i < 16; i++) {
            int idx = i * 128 + t;
            int m = idx >> 5, k = idx & 31;
            int kg = kb + kk + k;
            As[m][k] = fmaxf(g_h2pre[m * HH + kg] + b2[kg], 0.0f);
        }
        #pragma unroll
        for (int i = 0; i < 8; i++) {
            int idx = i * 128 + t;
            int k = idx >> 5, n = idx & 31;
            Bs[k][n] = W3[(kb + kk + k) * SS + nb + n];
        }
        __syncthreads();

        #pragma unroll
        for (int k = 0; k < 32; k++) {
            float4 b4 = *(const float4*)&Bs[k][n4];
            float a0 = As[m4 + 0][k];
            float a1 = As[m4 + 1][k];
            float a2 = As[m4 + 2][k];
            float a3 = As[m4 + 3][k];
            acc[0][0] += a0 * b4.x; acc[0][1] += a0 * b4.y; acc[0][2] += a0 * b4.z; acc[0][3] += a0 * b4.w;
            acc[1][0] += a1 * b4.x; acc[1][1] += a1 * b4.y; acc[1][2] += a1 * b4.z; acc[1][3] += a1 * b4.w;
            acc[2][0] += a2 * b4.x; acc[2][1] += a2 * b4.y; acc[2][2] += a2 * b4.z; acc[2][3] += a2 * b4.w;
            acc[3][0] += a3 * b4.x; acc[3][1] += a3 * b4.y; acc[3][2] += a3 * b4.z; acc[3][3] += a3 * b4.w;
        }
        __syncthreads();
    }

    #pragma unroll
    for (int i = 0; i < 4; i++)
        #pragma unroll
        for (int j = 0; j < 4; j++)
            atomicAdd(&out[(m4 + i) * SS + nb + n4 + j], acc[i][j]);

    // Restore the g_h1pre == 0 invariant for the next call/replay.
    // 64 CTAs x 128 threads = 8192 threads -> 4 elements each.
    const int base = (blockIdx.y * gridDim.x + blockIdx.x) * 128 + t;  // 0..8191
    #pragma unroll
    for (int i = 0; i < 4; i++)
        g_h1pre[base + i * 8192] = 0.0f;
}

// ---------------------------------------------------------------------------
extern "C" void kernel_launch(void* const* d_in, const int* in_sizes, int n_in,
                              void* d_out, int out_size) {
    const int*   x  = (const int*)d_in[0];     // int32 or int64, detected on device
    const float* W1 = (const float*)d_in[1];
    const float* b1 = (const float*)d_in[2];
    const float* W2 = (const float*)d_in[3];
    const float* b2 = (const float*)d_in[4];
    const float* W3 = (const float*)d_in[5];
    const float* b3 = (const float*)d_in[6];
    float* out = (float*)d_out;

    k_gather<<<dim3(256, NSPLIT), 128>>>(x, W1, b3, out);
    k_gemm1<<<dim3(16, 8), 128>>>(b1, W2);
    k_gemm2<<<dim3(8, 8), 128>>>(b2, W3, out);
}